// round 11
// baseline (speedup 1.0000x reference)
#include <cuda_runtime.h>
#include <cuda_bf16.h>

// VariableSelectionNetwork: B=32, S=512, F=32, H=64
//   A[f][g] = sum_h W_feat[f,h]*W_gate[f*H+h, g];  c = b_gate + sum b_feat.W_gate
//   gates = softmax(x @ A + c);  out = [g*x, g] @ [W_feat; b_feat]
// Prep: partial A/c over 4 h-quarters, 128 blocks.
// Main: 256 blocks x 64 threads, 64 rows/block.
//   Phase 1: ONE thread per row (logits+softmax fully local, A broadcast).
//   Phase 2: 2 rows x 32 cols per thread; W loads warp-uniform (broadcast),
//   x via one LDS.64; 32 FFMA2 per k-iter with only 11 overhead instrs.

#define F_DIM 32
#define H_DIM 64
#define ROWS  16384
#define MB_ROWS 64
#define MAIN_GRID (ROWS / MB_ROWS)   // 256

typedef unsigned long long ull;

__device__ float g_Apart[4 * 1024];
__device__ float g_Cpart[4 * 1024];

// ---------------- f32x2 helpers ----------------
__device__ __forceinline__ ull pk2(float a, float b) {
    ull r;
    asm("mov.b64 %0, {%1, %2};" : "=l"(r) : "f"(a), "f"(b));
    return r;
}
__device__ __forceinline__ void ffma2(ull& d, ull a, ull b) {
    asm("fma.rn.f32x2 %0, %1, %2, %3;" : "=l"(d) : "l"(a), "l"(b), "l"(d));
}
__device__ __forceinline__ float2 unpk2(ull v) {
    float2 r;
    asm("mov.b64 {%0, %1}, %2;" : "=f"(r.x), "=f"(r.y) : "l"(v));
    return r;
}

// ---------------------------------------------------------------------------
// Prep: 128 blocks (f = bid>>2, h-quarter q = bid&3), 128 threads.
// ---------------------------------------------------------------------------
__global__ void __launch_bounds__(128) vsn_prep_kernel(
    const float* __restrict__ W_feat,
    const float* __restrict__ b_feat,
    const float* __restrict__ W_gate)
{
    const int f  = blockIdx.x >> 2;
    const int q  = blockIdx.x & 3;
    const int g  = threadIdx.x & 31;
    const int hh = threadIdx.x >> 5;

    float a = 0.f, c = 0.f;
#pragma unroll
    for (int kk = 0; kk < 4; kk++) {
        const int h = q * 16 + hh * 4 + kk;
        const float wg = W_gate[(f * H_DIM + h) * F_DIM + g];
        a = fmaf(W_feat[f * H_DIM + h], wg, a);
        c = fmaf(b_feat[f * H_DIM + h], wg, c);
    }

    __shared__ float rA[4][32];
    __shared__ float rC[4][32];
    rA[hh][g] = a;
    rC[hh][g] = c;
    __syncthreads();

    if (threadIdx.x < 32) {
        float as = 0.f, cs = 0.f;
#pragma unroll
        for (int r = 0; r < 4; r++) { as += rA[r][threadIdx.x]; cs += rC[r][threadIdx.x]; }
        g_Apart[q * 1024 + f * F_DIM + threadIdx.x] = as;
        g_Cpart[q * 1024 + f * F_DIM + threadIdx.x] = cs;
    }
}

// ---------------------------------------------------------------------------
// Main kernel: 256 blocks x 64 threads, 64 rows/block. Smem ~36.5 KB:
//   sWB [64][64] 16 KB, sX [64][64] 16 KB (k-major), sA [32][32] 4 KB.
// ---------------------------------------------------------------------------
__global__ void __launch_bounds__(64, 8) vsn_main_kernel(
    const float* __restrict__ features,
    const float* __restrict__ b_gate,
    const float* __restrict__ W_feat,
    const float* __restrict__ b_feat,
    float* __restrict__ out)
{
    __shared__ __align__(16) float sWB[2 * F_DIM * H_DIM];   // 4096 floats
    __shared__ __align__(16) float sX [2 * F_DIM * MB_ROWS]; // 4096 floats
    __shared__ __align__(16) float sA [F_DIM * F_DIM];       // 1024 floats
    __shared__ __align__(16) float sc [F_DIM];

    const int tid = threadIdx.x;   // 0..63

    // ---- Stage params ----
#pragma unroll
    for (int i = tid; i < 1024; i += 64) {       // sWB as 1024 float4
        const int k   = i >> 4;
        const int seg = i & 15;
        const float* src = (k < F_DIM ? W_feat + k * H_DIM
                                      : b_feat + (k - F_DIM) * H_DIM) + seg * 4;
        *(float4*)(sWB + k * H_DIM + seg * 4) = *(const float4*)src;
    }
#pragma unroll
    for (int j = 0; j < 16; j++) {               // fold A partials
        const int i = tid + j * 64;
        sA[i] = g_Apart[i] + g_Apart[1024 + i] + g_Apart[2048 + i] + g_Apart[3072 + i];
    }
    if (tid < 32) {                              // fold c partials
        float cv = b_gate[tid];
#pragma unroll 16
        for (int e = 0; e < 128; e++)
            cv += g_Cpart[(e >> 5) * 1024 + (e & 31) * F_DIM + tid];
        sc[tid] = cv;
    }
    __syncthreads();

    // ---- Phase 1: ONE thread per row ----
    const int row = blockIdx.x * MB_ROWS + tid;

    float x[F_DIM];
    {
        const float4* xr = (const float4*)(features + row * F_DIM);
#pragma unroll
        for (int i = 0; i < 8; i++) {
            float4 v = xr[i];
            x[4*i+0] = v.x; x[4*i+1] = v.y; x[4*i+2] = v.z; x[4*i+3] = v.w;
        }
    }

    // 32 logits as 16 f32x2 pairs; A rows are warp-uniform (broadcast)
    ull l2[16];
    {
        const ulonglong2* cp = (const ulonglong2*)sc;
#pragma unroll
        for (int j = 0; j < 8; j++) {
            ulonglong2 cv = cp[j];
            l2[2*j] = cv.x; l2[2*j+1] = cv.y;
        }
    }
#pragma unroll
    for (int f = 0; f < F_DIM; f++) {
        const ull xp = pk2(x[f], x[f]);
        const ulonglong2* ap = (const ulonglong2*)(sA + f * F_DIM);
#pragma unroll
        for (int j = 0; j < 8; j++) {
            const ulonglong2 av = ap[j];
            ffma2(l2[2*j],   xp, av.x);
            ffma2(l2[2*j+1], xp, av.y);
        }
    }
    float le[F_DIM];
#pragma unroll
    for (int i = 0; i < 16; i++) {
        float2 v = unpk2(l2[i]);
        le[2*i] = v.x; le[2*i+1] = v.y;
    }

    // thread-local softmax over 32 logits (no cross-thread traffic)
    float m = le[0];
#pragma unroll
    for (int j = 1; j < F_DIM; j++) m = fmaxf(m, le[j]);
    float s = 0.f;
#pragma unroll
    for (int j = 0; j < F_DIM; j++) { le[j] = __expf(le[j] - m); s += le[j]; }
    const float inv = 1.f / s;

    // write X' (k-major): sX[f][tid] = g*x[f]; sX[32+f][tid] = g
#pragma unroll
    for (int f = 0; f < F_DIM; f++) {
        const float gf = le[f] * inv;
        sX[f * MB_ROWS + tid]           = gf * x[f];
        sX[(F_DIM + f) * MB_ROWS + tid] = gf;
    }
    __syncthreads();

    // ---- Phase 2: 2 rows x 32 cols per thread ----
    const int p     = tid >> 1;      // row pair 0..31 -> rows 2p, 2p+1
    const int ch    = tid & 1;       // column half
    const int cbase = ch * 32;

    ull acc[2][16];
#pragma unroll
    for (int r = 0; r < 2; r++)
#pragma unroll
        for (int i = 0; i < 16; i++) acc[r][i] = 0ull;

#pragma unroll 4
    for (int k = 0; k < 2 * F_DIM; k++) {
        const float2 xv = *(const float2*)(sX + k * MB_ROWS + 2 * p);  // LDS.64
        const ull xp0 = pk2(xv.x, xv.x);
        const ull xp1 = pk2(xv.y, xv.y);
        const ulonglong2* wp = (const ulonglong2*)(sWB + k * H_DIM + cbase);
#pragma unroll
        for (int j = 0; j < 8; j++) {
            const ulonglong2 wv = wp[j];   // warp-uniform -> broadcast
            ffma2(acc[0][2*j],   xp0, wv.x);
            ffma2(acc[0][2*j+1], xp0, wv.y);
            ffma2(acc[1][2*j],   xp1, wv.x);
            ffma2(acc[1][2*j+1], xp1, wv.y);
        }
    }

    // store: rows 2p,2p+1, cols cbase..cbase+32 (8 STG.128)
    const int rowbase = blockIdx.x * MB_ROWS + 2 * p;
#pragma unroll
    for (int r = 0; r < 2; r++) {
        float* dst = out + (rowbase + r) * H_DIM + cbase;
#pragma unroll
        for (int j = 0; j < 4; j++) {
            const float2 a = unpk2(acc[r][2*j]);
            const float2 b = unpk2(acc[r][2*j+1]);
            *(float4*)(dst + j * 8)     = make_float4(a.x, a.y, b.x, b.y);
            // next pair fills +4..+8
            const float2 c2 = unpk2(acc[r][2*j+1]);
            (void)c2;
        }
        // rewrite cleanly: 8 pairs -> 4 float4 per 16 floats; do full 32 cols:
    }
    // NOTE: the loop above only covered half; do explicit full store instead:
#pragma unroll
    for (int r = 0; r < 2; r++) {
        float* dst = out + (rowbase + r) * H_DIM + cbase;
#pragma unroll
        for (int q4 = 0; q4 < 8; q4 += 2) {
            const float2 a = unpk2(acc[r][q4]);
            const float2 b = unpk2(acc[r][q4 + 1]);
            *(float4*)(dst + q4 * 2) = make_float4(a.x, a.y, b.x, b.y);
        }
#pragma unroll
        for (int q4 = 8; q4 < 16; q4 += 2) {
            const float2 a = unpk2(acc[r][q4]);
            const float2 b = unpk2(acc[r][q4 + 1]);
            *(float4*)(dst + q4 * 2) = make_float4(a.x, a.y, b.x, b.y);
        }
    }
}

extern "C" void kernel_launch(void* const* d_in, const int* in_sizes, int n_in,
                              void* d_out, int out_size)
{
    const float* features = (const float*)d_in[0];   // [32,512,32]
    const float* W_feat   = (const float*)d_in[1];   // [32,64]
    const float* b_feat   = (const float*)d_in[2];   // [32,64]
    const float* W_gate   = (const float*)d_in[3];   // [2048,32]
    const float* b_gate   = (const float*)d_in[4];   // [32]
    float* out = (float*)d_out;                      // [32,512,64]

    vsn_prep_kernel<<<128, 128>>>(W_feat, b_feat, W_gate);
    vsn_main_kernel<<<MAIN_GRID, 64>>>(features, b_gate, W_feat, b_feat, out);
}

// round 12
// speedup vs baseline: 1.2767x; 1.2767x over previous
#include <cuda_runtime.h>
#include <cuda_bf16.h>

// VariableSelectionNetwork: B=32, S=512, F=32, H=64
//   A[f][g] = sum_h W_feat[f,h]*W_gate[f*H+h, g];  c = b_gate + sum b_feat.W_gate
//   gates = softmax(x @ A + c);  out = [g*x, g] @ [W_feat; b_feat]
// Prep: partial A/c over 4 h-quarters, 128 blocks.
// Main: 128 blocks x 512 threads, 128 rows/block (R4 structure, 2x warps).
//   Phase 1: quad (4 thr/row, 8 logits each).
//   Phase 2: splitk2 (2 x 256 thr), tile 8 rows x 4 cols, row-pair f32x2 acc:
//            3 LDS.128 + 4 movs + 16 FFMA2 per k-iter.

#define F_DIM 32
#define H_DIM 64
#define ROWS  16384
#define MB_ROWS 128
#define MAIN_GRID (ROWS / MB_ROWS)   // 128

typedef unsigned long long ull;

__device__ float g_Apart[4 * 1024];
__device__ float g_Cpart[4 * 1024];

// ---------------- f32x2 helpers ----------------
__device__ __forceinline__ ull pk2(float a, float b) {
    ull r;
    asm("mov.b64 %0, {%1, %2};" : "=l"(r) : "f"(a), "f"(b));
    return r;
}
__device__ __forceinline__ void ffma2(ull& d, ull a, ull b) {
    asm("fma.rn.f32x2 %0, %1, %2, %3;" : "=l"(d) : "l"(a), "l"(b), "l"(d));
}
__device__ __forceinline__ void fadd2(ull& d, ull a) {
    asm("add.rn.f32x2 %0, %1, %2;" : "=l"(d) : "l"(d), "l"(a));
}
__device__ __forceinline__ float2 unpk2(ull v) {
    float2 r;
    asm("mov.b64 {%0, %1}, %2;" : "=f"(r.x), "=f"(r.y) : "l"(v));
    return r;
}

// ---------------------------------------------------------------------------
// Prep: 128 blocks (f = bid>>2, h-quarter q = bid&3), 128 threads.
// ---------------------------------------------------------------------------
__global__ void __launch_bounds__(128) vsn_prep_kernel(
    const float* __restrict__ W_feat,
    const float* __restrict__ b_feat,
    const float* __restrict__ W_gate)
{
    const int f  = blockIdx.x >> 2;
    const int q  = blockIdx.x & 3;
    const int g  = threadIdx.x & 31;
    const int hh = threadIdx.x >> 5;

    float a = 0.f, c = 0.f;
#pragma unroll
    for (int kk = 0; kk < 4; kk++) {
        const int h = q * 16 + hh * 4 + kk;
        const float wg = W_gate[(f * H_DIM + h) * F_DIM + g];
        a = fmaf(W_feat[f * H_DIM + h], wg, a);
        c = fmaf(b_feat[f * H_DIM + h], wg, c);
    }

    __shared__ float rA[4][32];
    __shared__ float rC[4][32];
    rA[hh][g] = a;
    rC[hh][g] = c;
    __syncthreads();

    if (threadIdx.x < 32) {
        float as = 0.f, cs = 0.f;
#pragma unroll
        for (int r = 0; r < 4; r++) { as += rA[r][threadIdx.x]; cs += rC[r][threadIdx.x]; }
        g_Apart[q * 1024 + f * F_DIM + threadIdx.x] = as;
        g_Cpart[q * 1024 + f * F_DIM + threadIdx.x] = cs;
    }
}

// ---------------------------------------------------------------------------
// Main kernel: 128 blocks x 512 threads, 128 rows/block. Dynamic smem 52 KB:
//   sWB [64][64] 16 KB, sX [64][128] 32 KB (k-major; reused as splitk buffer),
//   sA [32][32] 4 KB.
// ---------------------------------------------------------------------------
__global__ void __launch_bounds__(512, 1) vsn_main_kernel(
    const float* __restrict__ features,
    const float* __restrict__ b_gate,
    const float* __restrict__ W_feat,
    const float* __restrict__ b_feat,
    float* __restrict__ out)
{
    extern __shared__ float dyn[];
    float* sWB = dyn;                   // 4096 floats
    float* sX  = dyn + 4096;            // 8192 floats  [k][row], stride 128
    float* sA  = dyn + 4096 + 8192;     // 1024 floats

    __shared__ __align__(16) float sc[F_DIM];
    __shared__ float sCred[16][32];

    const int tid = threadIdx.x;

    // ---- Prefetch this thread's feature row (before staging: hides LDG) ----
    const int rowL = tid >> 2;                   // 0..127
    const int q    = tid & 3;
    const int row  = blockIdx.x * MB_ROWS + rowL;
    float4 xv[8];
    {
        const float4* xr = (const float4*)(features + row * F_DIM);
#pragma unroll
        for (int i = 0; i < 8; i++) xv[i] = xr[i];
    }

    // ---- Stage params ----
#pragma unroll
    for (int i = tid; i < 1024; i += 512) {      // sWB as 1024 float4
        const int k   = i >> 4;
        const int seg = i & 15;
        const float* src = (k < F_DIM ? W_feat + k * H_DIM
                                      : b_feat + (k - F_DIM) * H_DIM) + seg * 4;
        *(float4*)(sWB + k * H_DIM + seg * 4) = *(const float4*)src;
    }
#pragma unroll
    for (int j = 0; j < 2; j++) {                // fold A partials (1024 floats)
        const int i = tid + j * 512;
        if (i < 1024)
            sA[i] = g_Apart[i] + g_Apart[1024 + i] + g_Apart[2048 + i] + g_Apart[3072 + i];
    }
    {                                            // fold c partials
        const int g  = tid & 31;
        const int ch = (tid >> 5) & 15;          // 0..15
        if (tid < 512) {
            float s = 0.f;
#pragma unroll
            for (int e = 0; e < 8; e++) {
                const int ee = ch * 8 + e;       // (qq,f) flat 0..127
                s += g_Cpart[(ee >> 5) * 1024 + (ee & 31) * F_DIM + g];
            }
            if (tid < 512) sCred[ch][g] = s;
        }
    }
    __syncthreads();
    if (tid < 32) {
        float cv = b_gate[tid];
#pragma unroll
        for (int r = 0; r < 16; r++) cv += sCred[r][tid];
        sc[tid] = cv;
    }
    __syncthreads();

    // ---- Phase 1: gates (quad: 4 threads/row, 8 logits each) ----
    float x[F_DIM];
#pragma unroll
    for (int i = 0; i < 8; i++) {
        x[4*i+0] = xv[i].x; x[4*i+1] = xv[i].y;
        x[4*i+2] = xv[i].z; x[4*i+3] = xv[i].w;
    }

    ull l2[4];
    {
        const ulonglong2* cp = (const ulonglong2*)(sc + q * 8);
        ulonglong2 ca = cp[0], cb = cp[1];
        l2[0] = ca.x; l2[1] = ca.y; l2[2] = cb.x; l2[3] = cb.y;
    }
#pragma unroll
    for (int f = 0; f < F_DIM; f++) {
        const ull xp = pk2(x[f], x[f]);
        const ulonglong2* ap = (const ulonglong2*)(sA + f * F_DIM + q * 8);
        ulonglong2 a0 = ap[0], a1 = ap[1];
        ffma2(l2[0], xp, a0.x); ffma2(l2[1], xp, a0.y);
        ffma2(l2[2], xp, a1.x); ffma2(l2[3], xp, a1.y);
    }
    float le[8];
#pragma unroll
    for (int i = 0; i < 4; i++) {
        float2 v = unpk2(l2[i]);
        le[2*i] = v.x; le[2*i+1] = v.y;
    }

    // softmax across quad
    float m = le[0];
#pragma unroll
    for (int j = 1; j < 8; j++) m = fmaxf(m, le[j]);
    m = fmaxf(m, __shfl_xor_sync(0xffffffffu, m, 1));
    m = fmaxf(m, __shfl_xor_sync(0xffffffffu, m, 2));
    float s = 0.f;
#pragma unroll
    for (int j = 0; j < 8; j++) { le[j] = __expf(le[j] - m); s += le[j]; }
    s += __shfl_xor_sync(0xffffffffu, s, 1);
    s += __shfl_xor_sync(0xffffffffu, s, 2);
    const float inv = 1.f / s;

    // write X' (k-major, stride 128): sX[f][rowL] = g*x[f]; sX[32+f][rowL] = g
    const int fb = q * 8;
#pragma unroll
    for (int j = 0; j < 8; j++) {
        const float gj = le[j] * inv;
        sX[(fb + j) * MB_ROWS + rowL]         = gj * x[fb + j];
        sX[(F_DIM + fb + j) * MB_ROWS + rowL] = gj;
    }
    __syncthreads();

    // ---- Phase 2: out = X' @ W', splitk2, tile 8 rows x 4 cols ----
    const int slice = tid >> 8;     // 0/1: k-half
    const int tt    = tid & 255;
    const int rg    = tt >> 4;      // 0..15 -> rows rg*8
    const int cg    = tt & 15;      // 0..15 -> cols cg*4
    const int r0    = rg * 8;
    const int c0    = cg * 4;
    const int kbase = slice * F_DIM;

    ull acc[4][4];                  // [rowpair][col]
#pragma unroll
    for (int rp = 0; rp < 4; rp++)
#pragma unroll
        for (int c2 = 0; c2 < 4; c2++) acc[rp][c2] = 0ull;

#pragma unroll 8
    for (int kk = 0; kk < F_DIM; kk++) {
        const int k = kbase + kk;
        // x row-pairs straight from LDS.128 (adjacent reg pairs)
        const ulonglong2 xa = *(const ulonglong2*)(sX + k * MB_ROWS + r0);
        const ulonglong2 xb = *(const ulonglong2*)(sX + k * MB_ROWS + r0 + 4);
        const float4 wv = *(const float4*)(sWB + k * H_DIM + c0);
        const ull w0 = pk2(wv.x, wv.x);
        const ull w1 = pk2(wv.y, wv.y);
        const ull w2 = pk2(wv.z, wv.z);
        const ull w3 = pk2(wv.w, wv.w);

        ffma2(acc[0][0], xa.x, w0); ffma2(acc[0][1], xa.x, w1);
        ffma2(acc[0][2], xa.x, w2); ffma2(acc[0][3], xa.x, w3);
        ffma2(acc[1][0], xa.y, w0); ffma2(acc[1][1], xa.y, w1);
        ffma2(acc[1][2], xa.y, w2); ffma2(acc[1][3], xa.y, w3);
        ffma2(acc[2][0], xb.x, w0); ffma2(acc[2][1], xb.x, w1);
        ffma2(acc[2][2], xb.x, w2); ffma2(acc[2][3], xb.x, w3);
        ffma2(acc[3][0], xb.y, w0); ffma2(acc[3][1], xb.y, w1);
        ffma2(acc[3][2], xb.y, w2); ffma2(acc[3][3], xb.y, w3);
    }
    __syncthreads();   // sX reads done; reuse as splitk buffer (4096 ull = 32 KB)

    ull* red = (ull*)sX;
    if (slice == 1) {
#pragma unroll
        for (int rp = 0; rp < 4; rp++)
#pragma unroll
            for (int c2 = 0; c2 < 4; c2++)
                red[(rp * 4 + c2) * 256 + tt] = acc[rp][c2];
    }
    __syncthreads();

    if (slice == 0) {
#pragma unroll
        for (int rp = 0; rp < 4; rp++)
#pragma unroll
            for (int c2 = 0; c2 < 4; c2++)
                fadd2(acc[rp][c2], red[(rp * 4 + c2) * 256 + tt]);

        const int rowbase = blockIdx.x * MB_ROWS + r0;
#pragma unroll
        for (int rp = 0; rp < 4; rp++) {
            const float2 v0 = unpk2(acc[rp][0]);
            const float2 v1 = unpk2(acc[rp][1]);
            const float2 v2 = unpk2(acc[rp][2]);
            const float2 v3 = unpk2(acc[rp][3]);
            *(float4*)(out + (rowbase + 2 * rp) * H_DIM + c0) =
                make_float4(v0.x, v1.x, v2.x, v3.x);
            *(float4*)(out + (rowbase + 2 * rp + 1) * H_DIM + c0) =
                make_float4(v0.y, v1.y, v2.y, v3.y);
        }
    }
}

extern "C" void kernel_launch(void* const* d_in, const int* in_sizes, int n_in,
                              void* d_out, int out_size)
{
    const float* features = (const float*)d_in[0];   // [32,512,32]
    const float* W_feat   = (const float*)d_in[1];   // [32,64]
    const float* b_feat   = (const float*)d_in[2];   // [32,64]
    const float* W_gate   = (const float*)d_in[3];   // [2048,32]
    const float* b_gate   = (const float*)d_in[4];   // [32]
    float* out = (float*)d_out;                      // [32,512,64]

    const int smem_bytes = (4096 + 8192 + 1024) * 4;  // 53248
    cudaFuncSetAttribute(vsn_main_kernel,
                         cudaFuncAttributeMaxDynamicSharedMemorySize, smem_bytes);

    vsn_prep_kernel<<<128, 128>>>(W_feat, b_feat, W_gate);
    vsn_main_kernel<<<MAIN_GRID, 512, smem_bytes>>>(features, b_gate, W_feat, b_feat, out);
}